// round 1
// baseline (speedup 1.0000x reference)
#include <cuda_runtime.h>
#include <cuda_bf16.h>

// Problem constants
#define BQ 8
#define NQ 8192
#define MK 2048
#define CC 256
#define EPSW 1e-8f

// Scratch: 3-NN indices + normalized weights per (b, n)
__device__ float g_w[BQ * NQ * 3];
__device__ int   g_i[BQ * NQ * 3];

// ---------------------------------------------------------------------------
// Kernel 1: three_nn + weight computation.
// Grid: (NQ / 512, BQ), block 256 threads, 2 queries per thread.
// All 2048 known points of batch b staged in smem as float4 (32 KB).
// ---------------------------------------------------------------------------
__global__ void __launch_bounds__(256) nn_kernel(
    const float* __restrict__ unknown,   // (B, N, 3)
    const float* __restrict__ known)     // (B, M, 3)
{
    __shared__ float4 sk[MK];

    const int b = blockIdx.y;
    const float* kb = known + (size_t)b * MK * 3;
    for (int i = threadIdx.x; i < MK; i += 256) {
        sk[i] = make_float4(kb[i * 3 + 0], kb[i * 3 + 1], kb[i * 3 + 2], 0.0f);
    }
    __syncthreads();

    // Two queries per thread: nA and nA + 256
    const int nA = blockIdx.x * 512 + threadIdx.x;
    const int nB = nA + 256;

    const float* uA = unknown + ((size_t)b * NQ + nA) * 3;
    const float* uB = unknown + ((size_t)b * NQ + nB) * 3;
    const float axv = uA[0], ayv = uA[1], azv = uA[2];
    const float bxv = uB[0], byv = uB[1], bzv = uB[2];

    float a0 = 1e30f, a1 = 1e30f, a2 = 1e30f;
    int   ai0 = 0, ai1 = 0, ai2 = 0;
    float c0 = 1e30f, c1 = 1e30f, c2 = 1e30f;
    int   ci0 = 0, ci1 = 0, ci2 = 0;

#pragma unroll 4
    for (int m = 0; m < MK; m++) {
        const float4 k = sk[m];

        float dx = axv - k.x, dy = ayv - k.y, dz = azv - k.z;
        float dA = fmaf(dx, dx, fmaf(dy, dy, dz * dz));

        float ex = bxv - k.x, ey = byv - k.y, ez = bzv - k.z;
        float dB = fmaf(ex, ex, fmaf(ey, ey, ez * ez));

        if (dA < a2) {
            if (dA < a1) {
                a2 = a1; ai2 = ai1;
                if (dA < a0) { a1 = a0; ai1 = ai0; a0 = dA; ai0 = m; }
                else         { a1 = dA; ai1 = m; }
            } else { a2 = dA; ai2 = m; }
        }
        if (dB < c2) {
            if (dB < c1) {
                c2 = c1; ci2 = ci1;
                if (dB < c0) { c1 = c0; ci1 = ci0; c0 = dB; ci0 = m; }
                else         { c1 = dB; ci1 = m; }
            } else { c2 = dB; ci2 = m; }
        }
    }

    // Weights: 1/(d2+eps), normalized
    {
        float r0 = 1.0f / (a0 + EPSW);
        float r1 = 1.0f / (a1 + EPSW);
        float r2 = 1.0f / (a2 + EPSW);
        float s  = 1.0f / (r0 + r1 + r2);
        int base = ((size_t)b * NQ + nA) * 3;
        g_w[base + 0] = r0 * s; g_w[base + 1] = r1 * s; g_w[base + 2] = r2 * s;
        g_i[base + 0] = ai0;    g_i[base + 1] = ai1;    g_i[base + 2] = ai2;
    }
    {
        float r0 = 1.0f / (c0 + EPSW);
        float r1 = 1.0f / (c1 + EPSW);
        float r2 = 1.0f / (c2 + EPSW);
        float s  = 1.0f / (r0 + r1 + r2);
        int base = ((size_t)b * NQ + nB) * 3;
        g_w[base + 0] = r0 * s; g_w[base + 1] = r1 * s; g_w[base + 2] = r2 * s;
        g_i[base + 0] = ci0;    g_i[base + 1] = ci1;    g_i[base + 2] = ci2;
    }
}

// ---------------------------------------------------------------------------
// Kernel 2: three_interpolate.
// Grid: (CC / CG, BQ), block 256 threads. Each block stages CG full feature
// rows f[b][c0..c0+CG][0:2048] in dynamic smem (CG*8KB), gathers from smem,
// writes out[b][c][n] coalesced over n.
// ---------------------------------------------------------------------------
#define CG 8

__global__ void __launch_bounds__(256) interp_kernel(
    const float* __restrict__ feats,     // (B, C, M)
    float* __restrict__ out)             // (B, C, N)
{
    extern __shared__ float rows[];      // CG * MK floats

    const int b  = blockIdx.y;
    const int c0 = blockIdx.x * CG;

    // Stage CG rows (contiguous in feats) via float4
    {
        const float4* f4 = (const float4*)(feats + ((size_t)b * CC + c0) * MK);
        float4* s4 = (float4*)rows;
        const int n4 = CG * MK / 4;
        for (int i = threadIdx.x; i < n4; i += 256) s4[i] = f4[i];
    }
    __syncthreads();

    for (int it = 0; it < NQ / 256; it++) {
        const int n = it * 256 + threadIdx.x;
        const int base = ((size_t)b * NQ + n) * 3;
        const int j0 = g_i[base + 0];
        const int j1 = g_i[base + 1];
        const int j2 = g_i[base + 2];
        const float w0 = g_w[base + 0];
        const float w1 = g_w[base + 1];
        const float w2 = g_w[base + 2];

#pragma unroll
        for (int j = 0; j < CG; j++) {
            const float* r = rows + j * MK;
            float v = fmaf(w0, r[j0], fmaf(w1, r[j1], w2 * r[j2]));
            out[((size_t)b * CC + c0 + j) * NQ + n] = v;
        }
    }
}

// ---------------------------------------------------------------------------
// Launch
// ---------------------------------------------------------------------------
extern "C" void kernel_launch(void* const* d_in, const int* in_sizes, int n_in,
                              void* d_out, int out_size)
{
    const float* unknown = (const float*)d_in[0];   // (8, 8192, 3)
    const float* known   = (const float*)d_in[1];   // (8, 2048, 3)
    const float* feats   = (const float*)d_in[2];   // (8, 256, 2048)
    float* out = (float*)d_out;                     // (8, 256, 8192)

    // Kernel 1: 3-NN + weights
    dim3 g1(NQ / 512, BQ);
    nn_kernel<<<g1, 256>>>(unknown, known);

    // Kernel 2: interpolation (needs 64 KB dynamic smem)
    static const int smem_bytes = CG * MK * (int)sizeof(float);
    cudaFuncSetAttribute(interp_kernel,
                         cudaFuncAttributeMaxDynamicSharedMemorySize, smem_bytes);
    dim3 g2(CC / CG, BQ);
    interp_kernel<<<g2, 256, smem_bytes>>>(feats, out);
}

// round 2
// speedup vs baseline: 1.3774x; 1.3774x over previous
#include <cuda_runtime.h>
#include <cuda_bf16.h>

// Problem constants
#define BQ 8
#define NQ 8192
#define MK 2048
#define CC 256
#define EPSW 1e-8f

// Scratch: 3-NN indices + normalized weights per (b, n)
__device__ float g_w[BQ * NQ * 3];
__device__ int   g_i[BQ * NQ * 3];

// ---------------------------------------------------------------------------
// f32x2 packed helpers (FFMA2 path — only reachable via PTX)
// ---------------------------------------------------------------------------
__device__ __forceinline__ unsigned long long fma2(unsigned long long a,
                                                   unsigned long long b,
                                                   unsigned long long c) {
    unsigned long long d;
    asm("fma.rn.f32x2 %0, %1, %2, %3;" : "=l"(d) : "l"(a), "l"(b), "l"(c));
    return d;
}
__device__ __forceinline__ unsigned long long pack2(float lo, float hi) {
    unsigned long long d;
    asm("mov.b64 %0, {%1, %2};" : "=l"(d) : "f"(lo), "f"(hi));
    return d;
}
__device__ __forceinline__ void unpack2(unsigned long long v, float& lo, float& hi) {
    asm("mov.b64 {%0, %1}, %2;" : "=f"(lo), "=f"(hi) : "l"(v));
}

// ---------------------------------------------------------------------------
// Kernel 1: three_nn + weights.
// Block 512 threads, 1 query/thread. Grid (NQ/512, BQ) = 128 blocks (1 wave).
// Known points staged packed-by-pairs:
//   sA[i] = (kx[2i], kx[2i+1], ky[2i], ky[2i+1])
//   sB[i] = (kz[2i], kz[2i+1], |k2i|^2, |k2i+1|^2)
// Loop computes score = |k|^2 - 2 u.k  (monotone in d^2) with 3 FFMA2 per
// 2 points. Exact d^2 recomputed for the 3 winners at the end.
// ---------------------------------------------------------------------------
__global__ void __launch_bounds__(512) nn_kernel(
    const float* __restrict__ unknown,   // (B, N, 3)
    const float* __restrict__ known)     // (B, M, 3)
{
    __shared__ float4 sA[MK / 2];
    __shared__ float4 sB[MK / 2];

    const int b = blockIdx.y;
    {
        const float2* kb2 = (const float2*)(known + (size_t)b * MK * 3);
        for (int i = threadIdx.x; i < MK / 2; i += 512) {
            float2 p0 = kb2[i * 3 + 0];   // x0 y0
            float2 p1 = kb2[i * 3 + 1];   // z0 x1
            float2 p2 = kb2[i * 3 + 2];   // y1 z1
            float w0 = fmaf(p0.x, p0.x, fmaf(p0.y, p0.y, p1.x * p1.x));
            float w1 = fmaf(p1.y, p1.y, fmaf(p2.x, p2.x, p2.y * p2.y));
            sA[i] = make_float4(p0.x, p1.y, p0.y, p2.x);
            sB[i] = make_float4(p1.x, p2.y, w0, w1);
        }
    }
    __syncthreads();

    const int n = blockIdx.x * 512 + threadIdx.x;
    const float* u = unknown + ((size_t)b * NQ + n) * 3;
    const float ux = u[0], uy = u[1], uz = u[2];

    const unsigned long long nx2 = pack2(-2.0f * ux, -2.0f * ux);
    const unsigned long long ny2 = pack2(-2.0f * uy, -2.0f * uy);
    const unsigned long long nz2 = pack2(-2.0f * uz, -2.0f * uz);

    float b0 = 1e30f, b1 = 1e30f, b2 = 1e30f;
    int   i0 = 0, i1 = 0, i2 = 0;

    const ulonglong2* pA = (const ulonglong2*)sA;
    const ulonglong2* pB = (const ulonglong2*)sB;

#pragma unroll 4
    for (int i = 0; i < MK / 2; i++) {
        ulonglong2 A = pA[i];   // A.x = kx pair, A.y = ky pair
        ulonglong2 Z = pB[i];   // Z.x = kz pair, Z.y = |k|^2 pair
        unsigned long long acc = fma2(nx2, A.x, fma2(ny2, A.y, fma2(nz2, Z.x, Z.y)));
        float s0, s1;
        unpack2(acc, s0, s1);

        if (fminf(s0, s1) < b2) {
            // rare path (~20x per 1024 iters)
            if (s0 < b2) {
                if (s0 < b1) {
                    b2 = b1; i2 = i1;
                    if (s0 < b0) { b1 = b0; i1 = i0; b0 = s0; i0 = 2 * i; }
                    else         { b1 = s0; i1 = 2 * i; }
                } else { b2 = s0; i2 = 2 * i; }
            }
            if (s1 < b2) {
                if (s1 < b1) {
                    b2 = b1; i2 = i1;
                    if (s1 < b0) { b1 = b0; i1 = i0; b0 = s1; i0 = 2 * i + 1; }
                    else         { b1 = s1; i1 = 2 * i + 1; }
                } else { b2 = s1; i2 = 2 * i + 1; }
            }
        }
    }

    // Exact d^2 for the 3 winners (weight formula is permutation-invariant).
    float d2v[3];
    int   idxv[3] = { i0, i1, i2 };
#pragma unroll
    for (int t = 0; t < 3; t++) {
        int m = idxv[t], h = m & 1, p = m >> 1;
        float kx = h ? sA[p].y : sA[p].x;
        float ky = h ? sA[p].w : sA[p].z;
        float kz = h ? sB[p].y : sB[p].x;
        float dx = ux - kx, dy = uy - ky, dz = uz - kz;
        d2v[t] = fmaf(dx, dx, fmaf(dy, dy, dz * dz));
    }

    float r0 = 1.0f / (d2v[0] + EPSW);
    float r1 = 1.0f / (d2v[1] + EPSW);
    float r2 = 1.0f / (d2v[2] + EPSW);
    float s  = 1.0f / (r0 + r1 + r2);
    int base = ((size_t)b * NQ + n) * 3;
    g_w[base + 0] = r0 * s; g_w[base + 1] = r1 * s; g_w[base + 2] = r2 * s;
    g_i[base + 0] = idxv[0]; g_i[base + 1] = idxv[1]; g_i[base + 2] = idxv[2];
}

// ---------------------------------------------------------------------------
// Kernel 2: three_interpolate.
// Grid (CC/CG, BQ, NSPLIT), block 256. Each block stages CG feature rows
// (64 KB smem), each thread handles 4 consecutive n -> STG.128 stores.
// ---------------------------------------------------------------------------
#define CG 8
#define NSPLIT 2
#define NPER (NQ / NSPLIT)

__global__ void __launch_bounds__(256) interp_kernel(
    const float* __restrict__ feats,     // (B, C, M)
    float* __restrict__ out)             // (B, C, N)
{
    extern __shared__ float rows[];      // CG * MK floats

    const int b  = blockIdx.y;
    const int c0 = blockIdx.x * CG;
    const int nbase = blockIdx.z * NPER;

    {
        const float4* f4 = (const float4*)(feats + ((size_t)b * CC + c0) * MK);
        float4* s4 = (float4*)rows;
        const int n4 = CG * MK / 4;
        for (int i = threadIdx.x; i < n4; i += 256) s4[i] = f4[i];
    }
    __syncthreads();

    float* outp = out + ((size_t)b * CC + c0) * NQ;

    for (int it = 0; it < NPER / 1024; it++) {
        const int n0 = nbase + it * 1024 + threadIdx.x * 4;

        const int4*   gi4 = (const int4*)  (g_i + ((size_t)b * NQ + n0) * 3);
        const float4* gw4 = (const float4*)(g_w + ((size_t)b * NQ + n0) * 3);
        int4   ia = gi4[0], ib = gi4[1], ic = gi4[2];
        float4 wa = gw4[0], wb = gw4[1], wc = gw4[2];

        // per-query neighbor (idx, weight) triples
        int   j00 = ia.x, j01 = ia.y, j02 = ia.z;
        int   j10 = ia.w, j11 = ib.x, j12 = ib.y;
        int   j20 = ib.z, j21 = ib.w, j22 = ic.x;
        int   j30 = ic.y, j31 = ic.z, j32 = ic.w;
        float w00 = wa.x, w01 = wa.y, w02 = wa.z;
        float w10 = wa.w, w11 = wb.x, w12 = wb.y;
        float w20 = wb.z, w21 = wb.w, w22 = wc.x;
        float w30 = wc.y, w31 = wc.z, w32 = wc.w;

#pragma unroll
        for (int ch = 0; ch < CG; ch++) {
            const float* r = rows + ch * MK;
            float4 v;
            v.x = fmaf(w00, r[j00], fmaf(w01, r[j01], w02 * r[j02]));
            v.y = fmaf(w10, r[j10], fmaf(w11, r[j11], w12 * r[j12]));
            v.z = fmaf(w20, r[j20], fmaf(w21, r[j21], w22 * r[j22]));
            v.w = fmaf(w30, r[j30], fmaf(w31, r[j31], w32 * r[j32]));
            *(float4*)(outp + (size_t)ch * NQ + n0) = v;
        }
    }
}

// ---------------------------------------------------------------------------
// Launch
// ---------------------------------------------------------------------------
extern "C" void kernel_launch(void* const* d_in, const int* in_sizes, int n_in,
                              void* d_out, int out_size)
{
    const float* unknown = (const float*)d_in[0];   // (8, 8192, 3)
    const float* known   = (const float*)d_in[1];   // (8, 2048, 3)
    const float* feats   = (const float*)d_in[2];   // (8, 256, 2048)
    float* out = (float*)d_out;                     // (8, 256, 8192)

    dim3 g1(NQ / 512, BQ);
    nn_kernel<<<g1, 512>>>(unknown, known);

    static const int smem_bytes = CG * MK * (int)sizeof(float);
    cudaFuncSetAttribute(interp_kernel,
                         cudaFuncAttributeMaxDynamicSharedMemorySize, smem_bytes);
    dim3 g2(CC / CG, BQ, NSPLIT);
    interp_kernel<<<g2, 256, smem_bytes>>>(feats, out);
}

// round 3
// speedup vs baseline: 2.1071x; 1.5297x over previous
#include <cuda_runtime.h>
#include <cuda_bf16.h>

#define BQ 8
#define NQ 8192
#define MK 2048
#define CC 256
#define EPSW 1e-8f
#define NGROUP (MK / 8)   // 256 groups of 8 points

// Compact per-query result: (w0, w1, bitcast(i0 | i1<<16), bitcast(i2))
__device__ float4 g_wp[BQ * NQ];

// ---------------------------------------------------------------------------
// f32x2 packed helpers
// ---------------------------------------------------------------------------
typedef unsigned long long u64t;
__device__ __forceinline__ u64t fma2(u64t a, u64t b, u64t c) {
    u64t d; asm("fma.rn.f32x2 %0, %1, %2, %3;" : "=l"(d) : "l"(a), "l"(b), "l"(c));
    return d;
}
__device__ __forceinline__ u64t add2(u64t a, u64t b) {
    u64t d; asm("add.rn.f32x2 %0, %1, %2;" : "=l"(d) : "l"(a), "l"(b));
    return d;
}
__device__ __forceinline__ u64t mul2(u64t a, u64t b) {
    u64t d; asm("mul.rn.f32x2 %0, %1, %2;" : "=l"(d) : "l"(a), "l"(b));
    return d;
}
__device__ __forceinline__ u64t pack2(float lo, float hi) {
    u64t d; asm("mov.b64 %0, {%1, %2};" : "=l"(d) : "f"(lo), "f"(hi));
    return d;
}
__device__ __forceinline__ void unpack2(u64t v, float& lo, float& hi) {
    asm("mov.b64 {%0, %1}, %2;" : "=f"(lo), "=f"(hi) : "l"(v));
}

// ---------------------------------------------------------------------------
// Kernel 1: three_nn + weights. Branchless group-of-8 top-3.
// Block 256, 1 query/thread, grid (NQ/256, BQ) = 256 blocks.
// smem: sXY[p] = (x_{2p}, x_{2p+1}, y_{2p}, y_{2p+1}) ; sZ[m] = z_m.
// Hot loop per group g (8 points): exact d^2 via packed add/fma/mul,
// min-tree, select-based insert of (groupmin, g). Finale re-derives exact
// top-3 indices from the 3 winning groups.
// ---------------------------------------------------------------------------
__global__ void __launch_bounds__(256) nn_kernel(
    const float* __restrict__ unknown,   // (B, N, 3)
    const float* __restrict__ known)     // (B, M, 3)
{
    __shared__ float4 sXY[MK / 2];   // 16 KB
    __shared__ float  sZ[MK];        // 8 KB

    const int b = blockIdx.y;
    {
        const float2* kb2 = (const float2*)(known + (size_t)b * MK * 3);
        for (int i = threadIdx.x; i < MK / 2; i += 256) {
            float2 p0 = kb2[i * 3 + 0];   // x0 y0
            float2 p1 = kb2[i * 3 + 1];   // z0 x1
            float2 p2 = kb2[i * 3 + 2];   // y1 z1
            sXY[i] = make_float4(p0.x, p1.y, p0.y, p2.x);
            sZ[2 * i]     = p1.x;
            sZ[2 * i + 1] = p2.y;
        }
    }
    __syncthreads();

    const int n = blockIdx.x * 256 + threadIdx.x;
    const float* u = unknown + ((size_t)b * NQ + n) * 3;
    const float ux = u[0], uy = u[1], uz = u[2];
    const u64t nux = pack2(-ux, -ux);
    const u64t nuy = pack2(-uy, -uy);
    const u64t nuz = pack2(-uz, -uz);

    // top-3 group mins (sorted ascending) + group ids
    float v0 = 1e30f, v1 = 1e30f, v2 = 1e30f;
    int   q0 = 0, q1 = 0, q2 = 0;

    const ulonglong2* pXY = (const ulonglong2*)sXY;
    const ulonglong2* pZ  = (const ulonglong2*)sZ;

#pragma unroll 2
    for (int g = 0; g < NGROUP; g++) {
        ulonglong2 A0 = pXY[4 * g + 0];
        ulonglong2 A1 = pXY[4 * g + 1];
        ulonglong2 A2 = pXY[4 * g + 2];
        ulonglong2 A3 = pXY[4 * g + 3];
        ulonglong2 Z0 = pZ[2 * g + 0];   // z[8g..8g+3]
        ulonglong2 Z1 = pZ[2 * g + 1];   // z[8g+4..8g+7]

        u64t dx0 = add2(A0.x, nux), dy0 = add2(A0.y, nuy), dz0 = add2(Z0.x, nuz);
        u64t dx1 = add2(A1.x, nux), dy1 = add2(A1.y, nuy), dz1 = add2(Z0.y, nuz);
        u64t dx2 = add2(A2.x, nux), dy2 = add2(A2.y, nuy), dz2 = add2(Z1.x, nuz);
        u64t dx3 = add2(A3.x, nux), dy3 = add2(A3.y, nuy), dz3 = add2(Z1.y, nuz);

        u64t a0 = fma2(dx0, dx0, fma2(dy0, dy0, mul2(dz0, dz0)));
        u64t a1 = fma2(dx1, dx1, fma2(dy1, dy1, mul2(dz1, dz1)));
        u64t a2 = fma2(dx2, dx2, fma2(dy2, dy2, mul2(dz2, dz2)));
        u64t a3 = fma2(dx3, dx3, fma2(dy3, dy3, mul2(dz3, dz3)));

        float s0, s1, s2, s3, s4, s5, s6, s7;
        unpack2(a0, s0, s1); unpack2(a1, s2, s3);
        unpack2(a2, s4, s5); unpack2(a3, s6, s7);

        float m = fminf(fminf(fminf(s0, s1), fminf(s2, s3)),
                        fminf(fminf(s4, s5), fminf(s6, s7)));

        // branchless sorted insert of (m, g); strict < keeps earlier (lower g)
        bool c0 = m < v0, c1 = m < v1, c2 = m < v2;
        float nv0 = c0 ? m  : v0;
        float nv1 = c0 ? v0 : (c1 ? m  : v1);
        float nv2 = c1 ? v1 : (c2 ? m  : v2);
        int   ng0 = c0 ? g  : q0;
        int   ng1 = c0 ? q0 : (c1 ? g  : q1);
        int   ng2 = c1 ? q1 : (c2 ? g  : q2);
        v0 = nv0; v1 = nv1; v2 = nv2;
        q0 = ng0; q1 = ng1; q2 = ng2;
    }

    // Sort winning group ids ascending so finale iterates in ascending m
    // (strict-< inserts then match jax top_k's lower-index tie-break).
    int ha = min(q0, min(q1, q2));
    int hc = max(q0, max(q1, q2));
    int hb = q0 + q1 + q2 - ha - hc;
    int grp[3] = { ha, hb, hc };

    // Finale: exact top-3 over the 24 candidate points.
    float d0 = 1e30f, d1 = 1e30f, d2v = 1e30f;
    int   i0 = 0, i1 = 0, i2 = 0;
#pragma unroll
    for (int t = 0; t < 3; t++) {
        const int mb = grp[t] * 8;
#pragma unroll
        for (int k = 0; k < 8; k++) {
            const int m = mb + k;
            const int p = m >> 1, h = m & 1;
            float4 XY = sXY[p];
            float kx = h ? XY.y : XY.x;
            float ky = h ? XY.w : XY.z;
            float kz = sZ[m];
            float dx = kx - ux, dy = ky - uy, dz = kz - uz;
            float d2 = fmaf(dx, dx, fmaf(dy, dy, dz * dz));
            bool c0b = d2 < d0, c1b = d2 < d1, c2b = d2 < d2v;
            float t0 = c0b ? d2 : d0;
            float t1 = c0b ? d0 : (c1b ? d2 : d1);
            float t2 = c1b ? d1 : (c2b ? d2 : d2v);
            int   j0 = c0b ? m  : i0;
            int   j1 = c0b ? i0 : (c1b ? m  : i1);
            int   j2 = c1b ? i1 : (c2b ? m  : i2);
            d0 = t0; d1 = t1; d2v = t2;
            i0 = j0; i1 = j1; i2 = j2;
        }
    }

    const float r0 = 1.0f / (d0 + EPSW);
    const float r1 = 1.0f / (d1 + EPSW);
    const float r2 = 1.0f / (d2v + EPSW);
    const float s  = 1.0f / (r0 + r1 + r2);
    g_wp[(size_t)b * NQ + n] =
        make_float4(r0 * s, r1 * s,
                    __int_as_float(i0 | (i1 << 16)),
                    __int_as_float(i2));
}

// ---------------------------------------------------------------------------
// Kernel 2: three_interpolate, m-major transposed smem.
// Grid (CC/4 = 64, BQ), block 256. smem rowsT[m][c0..c0+3] (32 KB).
// Each thread: 4 queries/iter; per query 3 LDS.128 gathers (4 channels each);
// stores as per-channel float4 (STG.128).
// ---------------------------------------------------------------------------
#define CG 4

__global__ void __launch_bounds__(256) interp_kernel(
    const float* __restrict__ feats,     // (B, C, M)
    float* __restrict__ out)             // (B, C, N)
{
    __shared__ float rowsT[MK * CG];     // 32 KB

    const int b  = blockIdx.y;
    const int c0 = blockIdx.x * CG;

    // Transposed staging: thread handles one m per iter; STS.128 conflict-free.
    {
        const float* fp = feats + ((size_t)b * CC + c0) * MK;
#pragma unroll
        for (int it = 0; it < MK / 256; it++) {
            const int m = it * 256 + threadIdx.x;
            float a = fp[m];
            float bb = fp[MK + m];
            float c = fp[2 * MK + m];
            float d = fp[3 * MK + m];
            *(float4*)&rowsT[m * 4] = make_float4(a, bb, c, d);
        }
    }
    __syncthreads();

    const float4* wp = (const float4*)&g_wp[(size_t)b * NQ];
    float* outp = out + ((size_t)b * CC + c0) * NQ;

    for (int it = 0; it < NQ / 1024; it++) {   // 8 iters
        const int n0 = it * 1024 + threadIdx.x * 4;

        float vq[4][4];   // [query][channel]
#pragma unroll
        for (int q = 0; q < 4; q++) {
            float4 W = wp[n0 + q];
            float w0 = W.x, w1 = W.y;
            float w2 = 1.0f - w0 - w1;
            unsigned pk = __float_as_uint(W.z);
            int j0 = pk & 0xFFFF;
            int j1 = pk >> 16;
            int j2 = __float_as_uint(W.w);

            float4 f0 = *(const float4*)&rowsT[j0 * 4];
            float4 f1 = *(const float4*)&rowsT[j1 * 4];
            float4 f2 = *(const float4*)&rowsT[j2 * 4];

            vq[q][0] = fmaf(w0, f0.x, fmaf(w1, f1.x, w2 * f2.x));
            vq[q][1] = fmaf(w0, f0.y, fmaf(w1, f1.y, w2 * f2.y));
            vq[q][2] = fmaf(w0, f0.z, fmaf(w1, f1.z, w2 * f2.z));
            vq[q][3] = fmaf(w0, f0.w, fmaf(w1, f1.w, w2 * f2.w));
        }

#pragma unroll
        for (int c = 0; c < CG; c++) {
            float4 v = make_float4(vq[0][c], vq[1][c], vq[2][c], vq[3][c]);
            *(float4*)(outp + (size_t)c * NQ + n0) = v;
        }
    }
}

// ---------------------------------------------------------------------------
// Launch
// ---------------------------------------------------------------------------
extern "C" void kernel_launch(void* const* d_in, const int* in_sizes, int n_in,
                              void* d_out, int out_size)
{
    const float* unknown = (const float*)d_in[0];   // (8, 8192, 3)
    const float* known   = (const float*)d_in[1];   // (8, 2048, 3)
    const float* feats   = (const float*)d_in[2];   // (8, 256, 2048)
    float* out = (float*)d_out;                     // (8, 256, 8192)

    dim3 g1(NQ / 256, BQ);
    nn_kernel<<<g1, 256>>>(unknown, known);

    dim3 g2(CC / CG, BQ);
    interp_kernel<<<g2, 256>>>(feats, out);
}

// round 4
// speedup vs baseline: 2.1097x; 1.0012x over previous
#include <cuda_runtime.h>
#include <cuda_bf16.h>

#define BQ 8
#define NQ 8192
#define MK 2048
#define CC 256
#define EPSW 1e-8f
#define NGROUP (MK / 8)   // 256 groups of 8 points

// Compact per-query result: (w0, w1, bitcast(i0 | i1<<16), bitcast(i2))
__device__ float4 g_wp[BQ * NQ];

// ---------------------------------------------------------------------------
// f32x2 packed helpers
// ---------------------------------------------------------------------------
typedef unsigned long long u64t;
__device__ __forceinline__ u64t fma2(u64t a, u64t b, u64t c) {
    u64t d; asm("fma.rn.f32x2 %0, %1, %2, %3;" : "=l"(d) : "l"(a), "l"(b), "l"(c));
    return d;
}
__device__ __forceinline__ u64t add2(u64t a, u64t b) {
    u64t d; asm("add.rn.f32x2 %0, %1, %2;" : "=l"(d) : "l"(a), "l"(b));
    return d;
}
__device__ __forceinline__ u64t mul2(u64t a, u64t b) {
    u64t d; asm("mul.rn.f32x2 %0, %1, %2;" : "=l"(d) : "l"(a), "l"(b));
    return d;
}
__device__ __forceinline__ u64t pack2(float lo, float hi) {
    u64t d; asm("mov.b64 %0, {%1, %2};" : "=l"(d) : "f"(lo), "f"(hi));
    return d;
}
__device__ __forceinline__ void unpack2(u64t v, float& lo, float& hi) {
    asm("mov.b64 {%0, %1}, %2;" : "=f"(lo), "=f"(hi) : "l"(v));
}

// ---------------------------------------------------------------------------
// Kernel 1: three_nn + weights. Branchless group-of-8 top-3.
// Block 128, 1 query/thread, grid (NQ/128, BQ) = 512 blocks (3.46/SM —
// good balance + enough warps/SMSP to hide the LDS->min-tree chain).
// ---------------------------------------------------------------------------
__global__ void __launch_bounds__(128) nn_kernel(
    const float* __restrict__ unknown,   // (B, N, 3)
    const float* __restrict__ known)     // (B, M, 3)
{
    __shared__ float4 sXY[MK / 2];   // 16 KB
    __shared__ float  sZ[MK];        // 8 KB

    const int b = blockIdx.y;
    {
        const float2* kb2 = (const float2*)(known + (size_t)b * MK * 3);
        for (int i = threadIdx.x; i < MK / 2; i += 128) {
            float2 p0 = kb2[i * 3 + 0];   // x0 y0
            float2 p1 = kb2[i * 3 + 1];   // z0 x1
            float2 p2 = kb2[i * 3 + 2];   // y1 z1
            sXY[i] = make_float4(p0.x, p1.y, p0.y, p2.x);
            sZ[2 * i]     = p1.x;
            sZ[2 * i + 1] = p2.y;
        }
    }
    __syncthreads();

    const int n = blockIdx.x * 128 + threadIdx.x;
    const float* u = unknown + ((size_t)b * NQ + n) * 3;
    const float ux = u[0], uy = u[1], uz = u[2];
    const u64t nux = pack2(-ux, -ux);
    const u64t nuy = pack2(-uy, -uy);
    const u64t nuz = pack2(-uz, -uz);

    // top-3 group mins (sorted ascending) + group ids
    float v0 = 1e30f, v1 = 1e30f, v2 = 1e30f;
    int   q0 = 0, q1 = 0, q2 = 0;

    const ulonglong2* pXY = (const ulonglong2*)sXY;
    const ulonglong2* pZ  = (const ulonglong2*)sZ;

#pragma unroll 4
    for (int g = 0; g < NGROUP; g++) {
        ulonglong2 A0 = pXY[4 * g + 0];
        ulonglong2 A1 = pXY[4 * g + 1];
        ulonglong2 A2 = pXY[4 * g + 2];
        ulonglong2 A3 = pXY[4 * g + 3];
        ulonglong2 Z0 = pZ[2 * g + 0];   // z[8g..8g+3]
        ulonglong2 Z1 = pZ[2 * g + 1];   // z[8g+4..8g+7]

        u64t dx0 = add2(A0.x, nux), dy0 = add2(A0.y, nuy), dz0 = add2(Z0.x, nuz);
        u64t dx1 = add2(A1.x, nux), dy1 = add2(A1.y, nuy), dz1 = add2(Z0.y, nuz);
        u64t dx2 = add2(A2.x, nux), dy2 = add2(A2.y, nuy), dz2 = add2(Z1.x, nuz);
        u64t dx3 = add2(A3.x, nux), dy3 = add2(A3.y, nuy), dz3 = add2(Z1.y, nuz);

        u64t a0 = fma2(dx0, dx0, fma2(dy0, dy0, mul2(dz0, dz0)));
        u64t a1 = fma2(dx1, dx1, fma2(dy1, dy1, mul2(dz1, dz1)));
        u64t a2 = fma2(dx2, dx2, fma2(dy2, dy2, mul2(dz2, dz2)));
        u64t a3 = fma2(dx3, dx3, fma2(dy3, dy3, mul2(dz3, dz3)));

        float s0, s1, s2, s3, s4, s5, s6, s7;
        unpack2(a0, s0, s1); unpack2(a1, s2, s3);
        unpack2(a2, s4, s5); unpack2(a3, s6, s7);

        float m = fminf(fminf(fminf(s0, s1), fminf(s2, s3)),
                        fminf(fminf(s4, s5), fminf(s6, s7)));

        // branchless sorted insert of (m, g); strict < keeps earlier (lower g)
        bool c0 = m < v0, c1 = m < v1, c2 = m < v2;
        float nv0 = c0 ? m  : v0;
        float nv1 = c0 ? v0 : (c1 ? m  : v1);
        float nv2 = c1 ? v1 : (c2 ? m  : v2);
        int   ng0 = c0 ? g  : q0;
        int   ng1 = c0 ? q0 : (c1 ? g  : q1);
        int   ng2 = c1 ? q1 : (c2 ? g  : q2);
        v0 = nv0; v1 = nv1; v2 = nv2;
        q0 = ng0; q1 = ng1; q2 = ng2;
    }

    // Sort winning group ids ascending so finale iterates in ascending index
    // (strict-< inserts then match jax top_k's lower-index tie-break).
    int ha = min(q0, min(q1, q2));
    int hc = max(q0, max(q1, q2));
    int hb = q0 + q1 + q2 - ha - hc;
    int grp[3] = { ha, hb, hc };

    // Finale: exact top-3 over the 24 candidate points.
    float d0 = 1e30f, d1 = 1e30f, d2v = 1e30f;
    int   i0 = 0, i1 = 0, i2 = 0;
#pragma unroll
    for (int t = 0; t < 3; t++) {
        const int mb = grp[t] * 8;
#pragma unroll
        for (int k = 0; k < 8; k++) {
            const int m = mb + k;
            const int p = m >> 1, h = m & 1;
            float4 XY = sXY[p];
            float kx = h ? XY.y : XY.x;
            float ky = h ? XY.w : XY.z;
            float kz = sZ[m];
            float dx = kx - ux, dy = ky - uy, dz = kz - uz;
            float d2 = fmaf(dx, dx, fmaf(dy, dy, dz * dz));
            bool c0b = d2 < d0, c1b = d2 < d1, c2b = d2 < d2v;
            float t0 = c0b ? d2 : d0;
            float t1 = c0b ? d0 : (c1b ? d2 : d1);
            float t2 = c1b ? d1 : (c2b ? d2 : d2v);
            int   j0 = c0b ? m  : i0;
            int   j1 = c0b ? i0 : (c1b ? m  : i1);
            int   j2 = c1b ? i1 : (c2b ? m  : i2);
            d0 = t0; d1 = t1; d2v = t2;
            i0 = j0; i1 = j1; i2 = j2;
        }
    }

    const float r0 = 1.0f / (d0 + EPSW);
    const float r1 = 1.0f / (d1 + EPSW);
    const float r2 = 1.0f / (d2v + EPSW);
    const float s  = 1.0f / (r0 + r1 + r2);
    g_wp[(size_t)b * NQ + n] =
        make_float4(r0 * s, r1 * s,
                    __int_as_float(i0 | (i1 << 16)),
                    __int_as_float(i2));
}

// ---------------------------------------------------------------------------
// Kernel 2: three_interpolate, m-major transposed smem.
// Grid (CC/4, BQ, NSPLIT=2) = 1024 blocks (6.9/SM vs smem cap 7), block 256.
// smem rowsT[m][c0..c0+3] (32 KB). Each thread: 4 queries/iter; per query
// 3 LDS.128 gathers; stores per-channel float4 (STG.128).
// ---------------------------------------------------------------------------
#define CG 4
#define NSPLIT 2
#define NPER (NQ / NSPLIT)

__global__ void __launch_bounds__(256) interp_kernel(
    const float* __restrict__ feats,     // (B, C, M)
    float* __restrict__ out)             // (B, C, N)
{
    __shared__ float rowsT[MK * CG];     // 32 KB

    const int b  = blockIdx.y;
    const int c0 = blockIdx.x * CG;
    const int nbase = blockIdx.z * NPER;

    // Transposed staging: thread handles one m per iter; STS.128 conflict-free.
    {
        const float* fp = feats + ((size_t)b * CC + c0) * MK;
#pragma unroll
        for (int it = 0; it < MK / 256; it++) {
            const int m = it * 256 + threadIdx.x;
            float a  = fp[m];
            float bb = fp[MK + m];
            float c  = fp[2 * MK + m];
            float d  = fp[3 * MK + m];
            *(float4*)&rowsT[m * 4] = make_float4(a, bb, c, d);
        }
    }
    __syncthreads();

    const float4* wp = (const float4*)&g_wp[(size_t)b * NQ];
    float* outp = out + ((size_t)b * CC + c0) * NQ;

    for (int it = 0; it < NPER / 1024; it++) {   // 4 iters
        const int n0 = nbase + it * 1024 + threadIdx.x * 4;

        float vq[4][4];   // [query][channel]
#pragma unroll
        for (int q = 0; q < 4; q++) {
            float4 W = wp[n0 + q];
            float w0 = W.x, w1 = W.y;
            float w2 = 1.0f - w0 - w1;
            unsigned pk = __float_as_uint(W.z);
            int j0 = pk & 0xFFFF;
            int j1 = pk >> 16;
            int j2 = __float_as_uint(W.w);

            float4 f0 = *(const float4*)&rowsT[j0 * 4];
            float4 f1 = *(const float4*)&rowsT[j1 * 4];
            float4 f2 = *(const float4*)&rowsT[j2 * 4];

            vq[q][0] = fmaf(w0, f0.x, fmaf(w1, f1.x, w2 * f2.x));
            vq[q][1] = fmaf(w0, f0.y, fmaf(w1, f1.y, w2 * f2.y));
            vq[q][2] = fmaf(w0, f0.z, fmaf(w1, f1.z, w2 * f2.z));
            vq[q][3] = fmaf(w0, f0.w, fmaf(w1, f1.w, w2 * f2.w));
        }

#pragma unroll
        for (int c = 0; c < CG; c++) {
            float4 v = make_float4(vq[0][c], vq[1][c], vq[2][c], vq[3][c]);
            *(float4*)(outp + (size_t)c * NQ + n0) = v;
        }
    }
}

// ---------------------------------------------------------------------------
// Launch
// ---------------------------------------------------------------------------
extern "C" void kernel_launch(void* const* d_in, const int* in_sizes, int n_in,
                              void* d_out, int out_size)
{
    const float* unknown = (const float*)d_in[0];   // (8, 8192, 3)
    const float* known   = (const float*)d_in[1];   // (8, 2048, 3)
    const float* feats   = (const float*)d_in[2];   // (8, 256, 2048)
    float* out = (float*)d_out;                     // (8, 256, 8192)

    dim3 g1(NQ / 128, BQ);
    nn_kernel<<<g1, 128>>>(unknown, known);

    dim3 g2(CC / CG, BQ, NSPLIT);
    interp_kernel<<<g2, 256>>>(feats, out);
}